// round 17
// baseline (speedup 1.0000x reference)
#include <cuda_runtime.h>
#include <math.h>

// x: (B=4, S=128, H=128, W=128) fp32 ; ada_mask: (B, S, K=21) fp32
// out[b,s,h,w] = sum_k softmax(ada_mask[b,s,:])[k] * xpad[b, s+k-10, h, w]
#define B_DIM    4
#define S_DIM    128
#define HW2_DIM  8192                  // H*W / 2 (float2 pixels per plane)
#define K_DIM    21
#define PAD      10
#define TILE_S   16                    // output rows (s) per thread
#define THREADS  128
#define WROW     24                    // weight row: 21 weights + 3 pad -> 96B, 16B-aligned rows
#define WIN      (TILE_S + K_DIM - 1)  // 36 planes per tile
#define BATCH1   21                    // front LDG batch = row 0's exact window

__global__ __launch_bounds__(THREADS, 5)
void AdaptiveMixing_28784870818046_kernel(const float2* __restrict__ x,
                                          const float*  __restrict__ ada_mask,
                                          float2* __restrict__ out)
{
    __shared__ __align__(16) float ws[TILE_S * WROW];   // every row float4-aligned

    const int b  = blockIdx.z;
    const int s0 = blockIdx.y * TILE_S;
    const int p  = blockIdx.x * THREADS + threadIdx.x;   // float2-pixel idx [0, HW2)

    const float2* xb = x + (size_t)b * S_DIM * HW2_DIM + p;

    // ---- batch 1: planes 0..20 (row 0's full window) — minimal front burst ----
    float2 win[WIN];
    #pragma unroll
    for (int i = 0; i < BATCH1; ++i) {
        const int s = s0 - PAD + i;
        win[i] = (s >= 0 && s < S_DIM) ? xb[(size_t)s * HW2_DIM]
                                       : make_float2(0.f, 0.f);
    }

    // ---- softmax overlaps batch-1 latency ----
    if (threadIdx.x < TILE_S) {
        const int s = s0 + threadIdx.x;
        const float* m = ada_mask + ((size_t)b * S_DIM + s) * K_DIM;
        float mv[K_DIM];
        float mx = -3.402823466e+38f;
        #pragma unroll
        for (int k = 0; k < K_DIM; ++k) { mv[k] = m[k]; mx = fmaxf(mx, mv[k]); }
        float sum = 0.f;
        #pragma unroll
        for (int k = 0; k < K_DIM; ++k) { mv[k] = expf(mv[k] - mx); sum += mv[k]; }
        const float inv = 1.0f / sum;
        float* row = ws + threadIdx.x * WROW;
        #pragma unroll
        for (int k = 0; k < K_DIM; ++k) row[k] = mv[k] * inv;
        row[21] = 0.f;
        row[22] = 0.f;
        row[23] = 0.f;
    }
    __syncthreads();

    // ---- 16 compute rows; remaining 15 planes issued ONE PER ROW (deep JIT):
    //      plane j+21 is loaded at the top of row j and first consumed as the
    //      final FMA of row j+1 (~1.3 rows of issue distance) ----
    float2* ob = out + ((size_t)b * S_DIM + s0) * HW2_DIM + p;
    #pragma unroll
    for (int j = 0; j < TILE_S; ++j) {
        if (j + K_DIM < WIN) {                           // rows 0..14: fetch plane j+21
            const int s = s0 + j + (K_DIM - PAD);        // s = s0 + j + 11 (top clip only)
            win[j + K_DIM] = (s < S_DIM) ? xb[(size_t)s * HW2_DIM]
                                         : make_float2(0.f, 0.f);
        }

        const float* row = ws + j * WROW;                // 96B-aligned: LDS.128 safe
        float a0x = 0.f, a0y = 0.f, a1x = 0.f, a1y = 0.f;  // 2 chains x 2 pixels
        #pragma unroll
        for (int q = 0; q < 5; ++q) {                      // k = 0..19 via float4 LDS
            const float4 w4 = reinterpret_cast<const float4*>(row)[q];
            const float2 v0 = win[j + 4*q + 0];
            const float2 v1 = win[j + 4*q + 1];
            const float2 v2 = win[j + 4*q + 2];
            const float2 v3 = win[j + 4*q + 3];
            a0x = fmaf(w4.x, v0.x, a0x);  a0y = fmaf(w4.x, v0.y, a0y);
            a1x = fmaf(w4.y, v1.x, a1x);  a1y = fmaf(w4.y, v1.y, a1y);
            a0x = fmaf(w4.z, v2.x, a0x);  a0y = fmaf(w4.z, v2.y, a0y);
            a1x = fmaf(w4.w, v3.x, a1x);  a1y = fmaf(w4.w, v3.y, a1y);
        }
        {                                                  // k = 20 singleton (last tap)
            const float w20 = row[20];
            const float2 v = win[j + 20];
            a0x = fmaf(w20, v.x, a0x);    a0y = fmaf(w20, v.y, a0y);
        }
        float2 r;
        r.x = a0x + a1x;
        r.y = a0y + a1y;
        ob[(size_t)j * HW2_DIM] = r;
    }
}

extern "C" void kernel_launch(void* const* d_in, const int* in_sizes, int n_in,
                              void* d_out, int out_size)
{
    const float2* x       = (const float2*)d_in[0];   // (4,128,128,128) fp32 as float2
    const float* ada_mask = (const float*)d_in[1];    // (4,128,21) fp32
    float2* out           = (float2*)d_out;

    dim3 grid(HW2_DIM / THREADS,   // 64 pixel-blocks
              S_DIM / TILE_S,      // 8 s-tiles
              B_DIM);              // 4 batches  => 2048 CTAs
    AdaptiveMixing_28784870818046_kernel<<<grid, THREADS>>>(x, ada_mask, out);
}